// round 15
// baseline (speedup 1.0000x reference)
#include <cuda_runtime.h>
#include <cuda_bf16.h>
#include <math.h>

#define NB 4
#define NN 2048
#define DD 128
#define KK 32
#define H1 530      // 2*EIN
#define H1P 544     // padded to 17*32
#define NBI (NB*NN) // 8192
#define NWARPS 2368 // 148 blocks * 16 warps

typedef unsigned long long ull;
typedef unsigned int uint;

// ---------------- scratch (static device globals; no allocation) ----------------
__device__ float g_A  [NBI * H1];         // feats_i @ W1[0:128]
__device__ float g_Bv [NBI * H1P + 160];  // feats_j @ W1[128:256], padded (zero-init)
__device__ float g_NH [NBI * 256];        // feats   @ node_w1[0:128]
__device__ float g_mi [NBI * 16];         // summed edge messages per node
__device__ float g_cm [NBI * 3];          // mean-centered coords
__device__ int   g_nbidx[NBI * KK];
__device__ float g_dk   [NBI * KK];

// ---------------- packed f32x2 primitives (Blackwell) ---------------------------
__device__ __forceinline__ ull pk2(float lo, float hi) {
    ull r; asm("mov.b64 %0,{%1,%2};" : "=l"(r) : "f"(lo), "f"(hi)); return r;
}
__device__ __forceinline__ void upk2(float& lo, float& hi, ull v) {
    asm("mov.b64 {%0,%1},%2;" : "=f"(lo), "=f"(hi) : "l"(v));
}
__device__ __forceinline__ ull fma2(ull a, ull b, ull c) {
    ull d; asm("fma.rn.f32x2 %0,%1,%2,%3;" : "=l"(d) : "l"(a), "l"(b), "l"(c)); return d;
}
__device__ __forceinline__ ull add2(ull a, ull b) {
    ull d; asm("add.rn.f32x2 %0,%1,%2;" : "=l"(d) : "l"(a), "l"(b)); return d;
}
__device__ __forceinline__ ull mul2(ull a, ull b) {
    ull d; asm("mul.rn.f32x2 %0,%1,%2;" : "=l"(d) : "l"(a), "l"(b)); return d;
}
__device__ __forceinline__ ull shflx64(ull v, int m) {
    uint lo, hi;
    asm("mov.b64 {%0,%1},%2;" : "=r"(lo), "=r"(hi) : "l"(v));
    lo = __shfl_xor_sync(0xffffffffu, lo, m);
    hi = __shfl_xor_sync(0xffffffffu, hi, m);
    ull r; asm("mov.b64 %0,{%1,%2};" : "=l"(r) : "r"(lo), "r"(hi)); return r;
}
// bf16x2 (u32) -> packed f32x2 (exact widening)
__device__ __forceinline__ ull bfp(uint v) {
    return pk2(__uint_as_float(v << 16), __uint_as_float(v & 0xffff0000u));
}
// bf16x2 math
__device__ __forceinline__ uint hfma2b(uint a, uint b, uint c) {
    uint d; asm("fma.rn.bf16x2 %0,%1,%2,%3;" : "=r"(d) : "r"(a), "r"(b), "r"(c)); return d;
}
__device__ __forceinline__ uint hadd2b(uint a, uint b) {
    uint d; asm("add.rn.bf16x2 %0,%1,%2;" : "=r"(d) : "r"(a), "r"(b)); return d;
}
__device__ __forceinline__ uint hmul2b(uint a, uint b) {
    uint d; asm("mul.rn.bf16x2 %0,%1,%2;" : "=r"(d) : "r"(a), "r"(b)); return d;
}
// pack two f32 into bf16x2: {hi, lo}
__device__ __forceinline__ uint cvt2(float hi, float lo) {
    uint d; asm("cvt.rn.bf16x2.f32 %0,%1,%2;" : "=r"(d) : "f"(hi), "f"(lo)); return d;
}
__device__ __forceinline__ uint cvtdup(float x) {
    uint d; asm("cvt.rn.bf16x2.f32 %0,%1,%1;" : "=r"(d) : "f"(x)); return d;
}

// packed f32x2 silu (Taylor; pre-activations are 60-sigma inside |x|<1)
#define SILU2(res, xin) do { \
    ull _x = (xin); \
    ull _x2 = mul2(_x, _x); \
    ull _s = fma2(CP4, _x2, CP3); \
    _s = fma2(_s, _x2, CP2); \
    _s = fma2(_s, _x2, CP1); \
    _s = fma2(_s, _x2, CP0); \
    ull _t = fma2(_x, _s, CHALF); \
    (res) = mul2(_x, _t); \
} while (0)

// packed bf16x2 silu
#define SILU2H(res, xin) do { \
    uint _x = (xin); \
    uint _x2 = hmul2b(_x, _x); \
    uint _s = hfma2b(HP4, _x2, HP3); \
    _s = hfma2b(_s, _x2, HP2); \
    _s = hfma2b(_s, _x2, HP1); \
    _s = hfma2b(_s, _x2, HP0); \
    uint _t = hfma2b(_x, _s, HHALF); \
    (res) = hmul2b(_x, _t); \
} while (0)

// ---------------- scalar fast SiLU (guarded; used in k_node) --------------------
__device__ __forceinline__ float silu_f(float x) {
    float ax = fabsf(x);
    if (ax < 1.0f) {
        float x2 = x * x;
        float s = 31.0f / 1451520.0f;
        s = fmaf(s, x2, -17.0f / 80640.0f);
        s = fmaf(s, x2,  1.0f / 480.0f);
        s = fmaf(s, x2, -1.0f / 48.0f);
        s = fmaf(s, x2,  0.25f);
        return x * fmaf(x, s, 0.5f);
    }
    return x / (1.0f + __expf(-x));
}

// ============ precomp GEMM: A, Bv, NH — 32 nodes/block, 8-node x 4-col units =====
__global__ void __launch_bounds__(256) k_precomp(const float* __restrict__ feats,
                                                 const float* __restrict__ ew1,
                                                 const float* __restrict__ nw1) {
    __shared__ float2 sfd[32 * 128];
    int n0 = blockIdx.x * 32;
    int t0 = threadIdx.x;
    for (int idx = t0; idx < 32 * 128; idx += 256) {
        float f = feats[(size_t)n0 * 128 + idx];
        sfd[idx] = make_float2(f, f);
    }
    __syncthreads();
    int lane = t0 & 31, wid = t0 >> 5;
    const ull* fd = (const ull*)sfd;

    #pragma unroll 1
    for (int u = wid; u < 28; u += 8) {
        int t = u >> 2, g = u & 3;
        const ull* fbase = fd + (size_t)(g * 8) * 128;
        if (t < 5) {
            int c = (t * 32 + lane) * 4;
            bool v0 = (c < H1);
            bool v1 = (c + 2 < H1);
            int cl = v0 ? c : 0;
            int ch = v1 ? (c + 2) : 0;
            ull aA0[8], aA1[8], aB0[8], aB1[8];
            #pragma unroll
            for (int i = 0; i < 8; i++) { aA0[i] = 0; aA1[i] = 0; aB0[i] = 0; aB1[i] = 0; }
            const float* wA  = ew1 + cl;
            const float* wAh = ew1 + ch;
            const float* wB  = ew1 + (size_t)128 * H1 + cl;
            const float* wBh = ew1 + (size_t)128 * H1 + ch;
            #pragma unroll 2
            for (int d = 0; d < 128; d++) {
                ull wa0 = *(const ull*)(wA  + (size_t)d * H1);
                ull wa1 = *(const ull*)(wAh + (size_t)d * H1);
                ull wb0 = *(const ull*)(wB  + (size_t)d * H1);
                ull wb1 = *(const ull*)(wBh + (size_t)d * H1);
                #pragma unroll
                for (int i = 0; i < 8; i++) {
                    ull fv = fbase[i * 128 + d];
                    aA0[i] = fma2(fv, wa0, aA0[i]);
                    aA1[i] = fma2(fv, wa1, aA1[i]);
                    aB0[i] = fma2(fv, wb0, aB0[i]);
                    aB1[i] = fma2(fv, wb1, aB1[i]);
                }
            }
            if (v0) {
                #pragma unroll
                for (int i = 0; i < 8; i++) {
                    int node = n0 + g * 8 + i;
                    *(ull*)&g_A [(size_t)node * H1  + c] = aA0[i];
                    *(ull*)&g_Bv[(size_t)node * H1P + c] = aB0[i];
                }
            }
            if (v1) {
                #pragma unroll
                for (int i = 0; i < 8; i++) {
                    int node = n0 + g * 8 + i;
                    *(ull*)&g_A [(size_t)node * H1  + c + 2] = aA1[i];
                    *(ull*)&g_Bv[(size_t)node * H1P + c + 2] = aB1[i];
                }
            }
        } else {
            int c = ((t - 5) * 32 + lane) * 4;
            ull a0[8], a1[8];
            #pragma unroll
            for (int i = 0; i < 8; i++) { a0[i] = 0; a1[i] = 0; }
            const float* w0 = nw1 + c;
            #pragma unroll 2
            for (int d = 0; d < 128; d++) {
                ull wa0 = *(const ull*)(w0 + (size_t)d * 256);
                ull wa1 = *(const ull*)(w0 + (size_t)d * 256 + 2);
                #pragma unroll
                for (int i = 0; i < 8; i++) {
                    ull fv = fbase[i * 128 + d];
                    a0[i] = fma2(fv, wa0, a0[i]);
                    a1[i] = fma2(fv, wa1, a1[i]);
                }
            }
            #pragma unroll
            for (int i = 0; i < 8; i++) {
                int node = n0 + g * 8 + i;
                *(ull*)&g_NH[(size_t)node * 256 + c]     = a0[i];
                *(ull*)&g_NH[(size_t)node * 256 + c + 2] = a1[i];
            }
        }
    }
}

// ============ topk via exact radix-8 select (4 passes) + mean --------------------
__global__ void __launch_bounds__(256) k_tm(const float* __restrict__ coors) {
    int blk = blockIdx.x;
    int t = threadIdx.x, lane = t & 31, wid = t >> 5;

    if (blk >= NBI) {
        int b = blk - NBI;
        __shared__ float rx[256], ry[256], rz[256];
        const float* cb = coors + (size_t)b * NN * 3;
        float sx = 0.f, sy = 0.f, sz = 0.f;
        for (int j = t; j < NN; j += 256) {
            sx += cb[3 * j]; sy += cb[3 * j + 1]; sz += cb[3 * j + 2];
        }
        rx[t] = sx; ry[t] = sy; rz[t] = sz;
        __syncthreads();
        for (int s = 128; s > 0; s >>= 1) {
            if (t < s) { rx[t] += rx[t + s]; ry[t] += ry[t + s]; rz[t] += rz[t + s]; }
            __syncthreads();
        }
        float mx = rx[0] * (1.0f / NN), my = ry[0] * (1.0f / NN), mz = rz[0] * (1.0f / NN);
        float* cmb = g_cm + (size_t)b * NN * 3;
        for (int j = t; j < NN; j += 256) {
            cmb[3 * j]     = cb[3 * j]     - mx;
            cmb[3 * j + 1] = cb[3 * j + 1] - my;
            cmb[3 * j + 2] = cb[3 * j + 2] - mz;
        }
        return;
    }

    int bi = blk;
    int b  = bi >> 11;
    __shared__ uint s_hist[256];
    __shared__ uint s_pref;
    __shared__ int s_kr, s_sel, s_curmin;
    __shared__ int s_cnt[8];

    const float* cb = coors + (size_t)b * NN * 3;
    float cx = coors[(size_t)bi * 3], cy = coors[(size_t)bi * 3 + 1], cz = coors[(size_t)bi * 3 + 2];
    float d[8]; unsigned ud[8];
    #pragma unroll
    for (int i = 0; i < 8; i++) {
        int j = t + i * 256;
        float dx = cx - cb[3 * j], dy = cy - cb[3 * j + 1], dz = cz - cb[3 * j + 2];
        float dv = dx * dx + dy * dy + dz * dz;
        d[i] = dv; ud[i] = __float_as_uint(dv);
    }
    if (t == 0) { s_pref = 0u; s_kr = KK; s_sel = 0; s_curmin = -1; }
    uint prefmask = 0u;

    // 4-pass radix-8 select (exact 32-bit key of the KK-th smallest)
    #pragma unroll 1
    for (int pass = 0; pass < 4; pass++) {
        int shift = 24 - pass * 8;
        s_hist[t] = 0u;
        __syncthreads();
        uint pref = s_pref;
        #pragma unroll
        for (int i = 0; i < 8; i++) {
            uint u = ud[i];
            if ((u & prefmask) == pref) atomicAdd(&s_hist[(u >> shift) & 255], 1u);
        }
        __syncthreads();
        if (t < 32) {
            uint h[8]; int tot = 0;
            #pragma unroll
            for (int i = 0; i < 8; i++) { h[i] = s_hist[t * 8 + i]; tot += (int)h[i]; }
            int incl = tot;
            #pragma unroll
            for (int off = 1; off < 32; off <<= 1) {
                int v = __shfl_up_sync(0xffffffffu, incl, off);
                if (t >= off) incl += v;
            }
            int excl = incl - tot;
            int kr = s_kr;
            if (excl < kr && kr <= incl) {
                int run = excl, dig = 7;
                for (int i = 0; i < 8; i++) {
                    if (run + (int)h[i] >= kr) { dig = i; break; }
                    run += (int)h[i];
                }
                s_pref = pref | ((uint)(t * 8 + dig) << shift);
                s_kr = kr - run;
            }
        }
        __syncthreads();
        prefmask |= (0xffu << shift);
    }
    uint thr = s_pref;

    // definite members: strictly below the exact threshold key
    #pragma unroll
    for (int i = 0; i < 8; i++) {
        if (ud[i] < thr) {
            int p = atomicAdd(&s_sel, 1);
            g_nbidx[(size_t)bi * KK + p] = t + i * 256;
            g_dk   [(size_t)bi * KK + p] = d[i];
        }
    }
    __syncthreads();
    // fill remaining with ties (== thr) by smallest index
    {
        int C = s_sel;
        for (int k = C; k < KK; k++) {
            int prev = s_curmin;
            int cand = 0x7fffffff;
            #pragma unroll
            for (int i = 0; i < 8; i++) {
                int j = t + i * 256;
                if (ud[i] == thr && j > prev && j < cand) cand = j;
            }
            #pragma unroll
            for (int off = 16; off; off >>= 1) {
                int o = __shfl_xor_sync(0xffffffffu, cand, off);
                cand = min(cand, o);
            }
            if (lane == 0) s_cnt[wid] = cand;
            __syncthreads();
            if (t == 0) {
                int mn2 = s_cnt[0];
                #pragma unroll
                for (int w = 1; w < 8; w++) mn2 = min(mn2, s_cnt[w]);
                g_nbidx[(size_t)bi * KK + k] = mn2;
                g_dk   [(size_t)bi * KK + k] = __uint_as_float(thr);
                s_curmin = mn2;
            }
            __syncthreads();
        }
    }
}

// ---------------- 32-bit bf16x2 reduce-scatter step ------------------------------
template <int MASK, int HALF>
__device__ __forceinline__ void rstep32(uint* q, int lane) {
    bool hi = (lane & MASK) != 0;
    #pragma unroll
    for (int i = 0; i < HALF; i++) {
        uint sent = hi ? q[i] : q[HALF + i];
        uint recv = __shfl_xor_sync(0xffffffffu, sent, MASK);
        q[i] = hadd2b(hi ? q[HALF + i] : q[i], recv);
    }
}

// ---------------- smem layout (float/u32 units) for k_main -----------------------
#define O_W1D   0                  // 9 rows dup bf16x2: 2x(544 uint4) + 544 u32 = 4896
#define O_W2D   4896               // 16 channels dup: 4 planes x 544 uint4 = 8704
#define O_CXW1  13600              // 2048
#define O_CXB1  15648              // 128
#define O_CXW2  15776              // 128
#define O_B2D   15904              // 32 (16 dup-pairs f32)
#define O_EB1   15936              // 544
#define O_BASEW 16480              // 16 warps * 544 = 8704
#define O_ENCW  25184              // 16 warps * 288 f32 = 4608
#define O_M     29792              // 16 warps * 32 = 512
#define O_MD    30304              // 16 warps * 64 = 1024
#define O_NBW   31328              // 512
#define SMEM_FLOATS 31840
#define SMEM_BYTES (SMEM_FLOATS * 4)

// ---------------- fused edge MLP + coord update (1 block/SM, warp-per-node) ------
__global__ void __launch_bounds__(512, 1) k_main(
    const float* __restrict__ coors,
    const float* __restrict__ ew1,  const float* __restrict__ eb1,
    const float* __restrict__ ew2,  const float* __restrict__ eb2,
    const float* __restrict__ cw1g, const float* __restrict__ cb1g,
    const float* __restrict__ cw2g, const float* __restrict__ cb2g,
    const float* __restrict__ xw1g, const float* __restrict__ xb1g,
    const float* __restrict__ xw2g, const float* __restrict__ xb2g,
    float* __restrict__ out)
{
    extern __shared__ float smx[];
    uint*  s_w1u  = (uint*)(smx + O_W1D);
    uint*  s_w2u  = (uint*)(smx + O_W2D);
    float* s_cxw1 = smx + O_CXW1;
    float* s_cxb1 = smx + O_CXB1;
    float* s_cxw2 = smx + O_CXW2;
    float* s_b2d  = smx + O_B2D;
    float* s_eb1  = smx + O_EB1;

    int tid = threadIdx.x;
    int lane = tid & 31, wid = tid >> 5;

    float* s_wbase = smx + O_BASEW + wid * 544;
    float* s_wenc  = smx + O_ENCW  + wid * 288;
    float* s_wm    = smx + O_M     + wid * 32;
    ull*   smd64   = (ull*)(smx + O_MD + wid * 64);
    int*   s_wnb   = (int*)(smx + O_NBW) + wid * 32;

    // ---- stage weights once per SM ----
    for (int idx = tid; idx < 4896; idx += 512) {
        int el, r;
        if (idx < 2176)      { el = idx >> 2; r = idx & 3; }
        else if (idx < 4352) { el = (idx - 2176) >> 2; r = 4 + (idx & 3); }
        else                 { el = idx - 4352; r = 8; }
        float a = (el < H1) ? ew1[(size_t)(256 + r) * H1 + el] : 0.f;
        s_w1u[idx] = cvtdup(a);
    }
    for (int idx = tid; idx < 8704; idx += 512) {
        int p = idx / 2176, rem = idx - p * 2176;
        int el = rem >> 2, sub = rem & 3;
        int c = p * 4 + sub;
        float a = (el < H1) ? ew2[(size_t)el * 16 + c] : 0.f;
        s_w2u[idx] = cvtdup(a);
    }
    for (int idx = tid; idx < 2048; idx += 512) {
        int c = idx >> 7, r = (idx >> 2) & 31, f = idx & 3;
        float v;
        if (f == 0)      v = cw1g[c * 64 + r];
        else if (f == 1) v = xw1g[c * 64 + r];
        else if (f == 2) v = cw1g[c * 64 + 32 + r];
        else             v = xw1g[c * 64 + 32 + r];
        s_cxw1[idx] = v;
    }
    if (tid < 128) {
        int l = tid >> 1, w = tid & 1;
        s_cxb1[tid] = w ? xb1g[l] : cb1g[l];
        s_cxw2[tid] = w ? xw2g[l] : cw2g[l];
    }
    if (tid < 32) s_b2d[tid] = eb2[tid >> 1];
    for (int idx = tid; idx < 544; idx += 512)
        s_eb1[idx] = (idx < H1) ? eb1[idx] : 0.f;
    __syncthreads();   // the ONLY block barrier

    const uint4* w1a4 = (const uint4*)(s_w1u);            // rows 0-3 dup
    const uint4* w1b4 = (const uint4*)(s_w1u + 2176);     // rows 4-7 dup
    const uint*  w1c1 = s_w1u + 4352;                     // row 8 dup
    const uint4* w2d4 = (const uint4*)s_w2u;              // 4 planes of 4 channels
    const ull* b2d_64 = (const ull*)s_b2d;
    const ulonglong2* cxw1q = (const ulonglong2*)s_cxw1;
    const ull* cxb1_64 = (const ull*)s_cxb1;
    const ull* cxw2_64 = (const ull*)s_cxw2;

    const ull CP4 = pk2(31.0f / 1451520.0f, 31.0f / 1451520.0f);
    const ull CP3 = pk2(-17.0f / 80640.0f, -17.0f / 80640.0f);
    const ull CP2 = pk2(1.0f / 480.0f, 1.0f / 480.0f);
    const ull CP1 = pk2(-1.0f / 48.0f, -1.0f / 48.0f);
    const ull CP0 = pk2(0.25f, 0.25f);
    const ull CHALF = pk2(0.5f, 0.5f);
    const uint HP4 = cvtdup(31.0f / 1451520.0f);
    const uint HP3 = cvtdup(-17.0f / 80640.0f);
    const uint HP2 = cvtdup(1.0f / 480.0f);
    const uint HP1 = cvtdup(-1.0f / 48.0f);
    const uint HP0 = cvtdup(0.25f);
    const uint HHALF = cvtdup(0.5f);

    float cb2r = cb2g[0], xb2r = xb2g[0];
    ull cxb1A = cxb1_64[lane], cxb1B = cxb1_64[lane + 32];
    ull cxw2A = cxw2_64[lane], cxw2B = cxw2_64[lane + 32];

    int r0 = wid * 148 + blockIdx.x;

    #pragma unroll 1
    for (int kk = 0; kk < 4; kk++) {
        int bi = r0 + kk * NWARPS;
        if (bi >= NBI) break;
        int b  = bi >> 11;

        for (int c = lane; c < H1P; c += 32)
            s_wbase[c] = (c < H1) ? (g_A[(size_t)bi * H1 + c] + s_eb1[c]) : 0.f;
        {
            float dv = g_dk[(size_t)bi * KK + lane];
            float* ev = s_wenc + lane * 9;
            ev[0] = sinf(dv);
            ev[1] = sinf(0.5f * dv);
            ev[2] = sinf(0.25f * dv);
            ev[3] = sinf(0.125f * dv);
            ev[4] = cosf(dv);
            ev[5] = cosf(0.5f * dv);
            ev[6] = cosf(0.25f * dv);
            ev[7] = cosf(0.125f * dv);
            ev[8] = dv;
            s_wnb[lane] = g_nbidx[(size_t)bi * KK + lane];
        }
        float ci0 = coors[(size_t)bi * 3 + 0];
        float ci1 = coors[(size_t)bi * 3 + 1];
        float ci2 = coors[(size_t)bi * 3 + 2];
        float ai0 = g_cm[(size_t)bi * 3 + 0];
        float ai1 = g_cm[(size_t)bi * 3 + 1];
        float ai2 = g_cm[(size_t)bi * 3 + 2];
        const float* cb3 = coors + (size_t)b * NN * 3;
        const float* cmb = g_cm  + (size_t)b * NN * 3;
        __syncwarp();

        float caccl = 0.f;
        float maccr = 0.f;

        #pragma unroll 1
        for (int pass = 0; pass < 16; pass++) {
            int e0 = pass * 2;
            int j0 = s_wnb[e0], j1 = s_wnb[e0 + 1];
            const float* bv0 = g_Bv + ((size_t)b * NN + j0) * H1P;
            const float* bv1 = g_Bv + ((size_t)b * NN + j1) * H1P;
            // enc edge-packed per row: (e0_r, e1_r)
            uint ep[9];
            #pragma unroll
            for (int r = 0; r < 9; r++)
                ep[r] = cvt2(s_wenc[(e0 + 1) * 9 + r], s_wenc[e0 * 9 + r]);

            uint q[16];
            #pragma unroll
            for (int i = 0; i < 16; i++) q[i] = 0u;

            float bc0 = bv0[lane],      bc1 = bv1[lane];
            float bn0 = bv0[lane + 32], bn1 = bv1[lane + 32];
            #pragma unroll 1
            for (int tt = 0; tt < 17; tt++) {
                int el = tt * 32 + lane;
                float bf0 = bv0[el + 64];
                float bf1 = bv1[el + 64];
                float base = s_wbase[el];
                uint4 wA = w1a4[el];
                uint4 wB = w1b4[el];
                uint  wC = w1c1[el];
                uint s = hmul2b(ep[0], wA.x);
                s = hfma2b(ep[1], wA.y, s);
                s = hfma2b(ep[2], wA.z, s);
                s = hfma2b(ep[3], wA.w, s);
                s = hfma2b(ep[4], wB.x, s);
                s = hfma2b(ep[5], wB.y, s);
                s = hfma2b(ep[6], wB.z, s);
                s = hfma2b(ep[7], wB.w, s);
                s = hfma2b(ep[8], wC,   s);
                uint bp = cvt2(base + bc1, base + bc0);
                uint pre = hadd2b(s, bp);
                uint h; SILU2H(h, pre);
                uint4 w20 = w2d4[el];
                uint4 w21 = w2d4[544 + el];
                uint4 w22 = w2d4[1088 + el];
                uint4 w23 = w2d4[1632 + el];
                q[0]  = hfma2b(h, w20.x, q[0]);
                q[1]  = hfma2b(h, w20.y, q[1]);
                q[2]  = hfma2b(h, w20.z, q[2]);
                q[3]  = hfma2b(h, w20.w, q[3]);
                q[4]  = hfma2b(h, w21.x, q[4]);
                q[5]  = hfma2b(h, w21.y, q[5]);
                q[6]  = hfma2b(h, w21.z, q[6]);
                q[7]  = hfma2b(h, w21.w, q[7]);
                q[8]  = hfma2b(h, w22.x, q[8]);
                q[9]  = hfma2b(h, w22.y, q[9]);
                q[10] = hfma2b(h, w22.z, q[10]);
                q[11] = hfma2b(h, w22.w, q[11]);
                q[12] = hfma2b(h, w23.x, q[12]);
                q[13] = hfma2b(h, w23.y, q[13]);
                q[14] = hfma2b(h, w23.z, q[14]);
                q[15] = hfma2b(h, w23.w, q[15]);
                bc0 = bn0; bc1 = bn1; bn0 = bf0; bn1 = bf1;
            }

            // reduce-scatter over 16 channel values (each = (e0,e1) pair)
            rstep32<16, 8>(q, lane);
            rstep32<8, 4>(q, lane);
            rstep32<4, 2>(q, lane);
            rstep32<2, 1>(q, lane);
            q[0] = hadd2b(q[0], __shfl_xor_sync(0xffffffffu, q[0], 1));

            {
                int ch = (lane >> 1) & 15;
                ull mb; SILU2(mb, add2(bfp(q[0]), b2d_64[ch]));
                if ((lane & 1) == 0) {
                    float m0, m1; upk2(m0, m1, mb);   // m0 = edge0, m1 = edge1
                    s_wm[ch] = m0 + m1;
                    smd64[2 * ch]     = pk2(m0, m0);
                    smd64[2 * ch + 1] = pk2(m1, m1);
                }
            }
            __syncwarp();
            if (lane < 16) maccr += s_wm[lane];

            // coor + cross MLPs (f32 packed), both edges share weight reads
            ull hA0 = cxb1A, hA1 = cxb1B;
            ull hB0 = cxb1A, hB1 = cxb1B;
            {
                const ulonglong2* mdq = (const ulonglong2*)smd64;
                #pragma unroll
                for (int c = 0; c < 16; c++) {
                    ulonglong2 wv = cxw1q[c * 32 + lane];
                    ulonglong2 mm = mdq[c];
                    hA0 = fma2(mm.x, wv.x, hA0); hA1 = fma2(mm.x, wv.y, hA1);
                    hB0 = fma2(mm.y, wv.x, hB0); hB1 = fma2(mm.y, wv.y, hB1);
                }
            }
            #pragma unroll 1
            for (int e = 0; e < 2; e++) {
                ull p0 = e ? hB0 : hA0;
                ull p1 = e ? hB1 : hA1;
                ull sA, sB;
                SILU2(sA, p0);
                SILU2(sB, p1);
                ull tt2 = mul2(sA, cxw2A);
                tt2 = fma2(sB, cxw2B, tt2);
                #pragma unroll
                for (int off = 16; off > 0; off >>= 1)
                    tt2 = add2(tt2, shflx64(tt2, off));
                float cw, xw; upk2(cw, xw, tt2);
                cw += cb2r; xw += xb2r;

                int j = (e == 0) ? j0 : j1;
                float cj0 = cb3[3 * j], cj1 = cb3[3 * j + 1], cj2 = cb3[3 * j + 2];
                float bj0 = cmb[3 * j], bj1 = cmb[3 * j + 1], bj2 = cmb[3 * j + 2];
                float rr, xx;
                if (lane == 0)      { rr = ci0 - cj0; xx = ai1 * bj2 - ai2 * bj1; }
                else if (lane == 1) { rr = ci1 - cj1; xx = ai2 * bj0 - ai0 * bj2; }
                else                { rr = ci2 - cj2; xx = ai0 * bj1 - ai1 * bj0; }
                if (lane < 3) caccl = fmaf(cw, rr, fmaf(xw, xx, caccl));
            }
        }

        if (lane < 16) g_mi[(size_t)bi * 16 + lane] = maccr;
        if (lane < 3) {
            float* outc = out + (size_t)NBI * DD;
            outc[(size_t)bi * 3 + lane] = coors[(size_t)bi * 3 + lane] + caccl;
        }
        __syncwarp();
    }
}

// ---------------- node MLP: 16 nodes per block -----------------------------------
__global__ void __launch_bounds__(256) k_node(
    const float* __restrict__ feats,
    const float* __restrict__ nw1, const float* __restrict__ nb1,
    const float* __restrict__ nw2, const float* __restrict__ nb2,
    float* __restrict__ out)
{
    __shared__ float s_nw1[16 * 256];
    __shared__ float s_m[16 * 16];
    __shared__ float s_hid[16 * 256];
    int n0 = blockIdx.x * 16;
    int tid = threadIdx.x;

    for (int idx = tid; idx < 4096; idx += 256) {
        int c = idx >> 8, col = idx & 255;
        s_nw1[idx] = nw1[(size_t)(128 + c) * 256 + col];
    }
    s_m[tid] = g_mi[(size_t)n0 * 16 + tid];
    __syncthreads();

    {
        float bcol = nb1[tid];
        #pragma unroll 1
        for (int node = 0; node < 16; node++) {
            float hv = g_NH[(size_t)(n0 + node) * 256 + tid] + bcol;
            #pragma unroll
            for (int c = 0; c < 16; c++)
                hv = fmaf(s_m[node * 16 + c], s_nw1[c * 256 + tid], hv);
            s_hid[node * 256 + tid] = silu_f(hv);
        }
    }
    __syncthreads();

    {
        int col = tid & 127, g = tid >> 7;
        const float* hh = s_hid + g * 8 * 256;
        float acc[8];
        #pragma unroll
        for (int nn = 0; nn < 8; nn++) acc[nn] = 0.f;
        #pragma unroll 4
        for (int k = 0; k < 256; k++) {
            float w = nw2[(size_t)k * 128 + col];
            #pragma unroll
            for (int nn = 0; nn < 8; nn++)
                acc[nn] = fmaf(hh[nn * 256 + k], w, acc[nn]);
        }
        float bb = nb2[col];
        #pragma unroll
        for (int nn = 0; nn < 8; nn++) {
            int node = n0 + g * 8 + nn;
            out[(size_t)node * 128 + col] = acc[nn] + bb + feats[(size_t)node * 128 + col];
        }
    }
}

extern "C" void kernel_launch(void* const* d_in, const int* in_sizes, int n_in,
                              void* d_out, int out_size) {
    const float* feats = (const float*)d_in[0];
    const float* coors = (const float*)d_in[1];
    const float* ew1   = (const float*)d_in[2];
    const float* eb1   = (const float*)d_in[3];
    const float* ew2   = (const float*)d_in[4];
    const float* eb2   = (const float*)d_in[5];
    const float* cw1   = (const float*)d_in[6];
    const float* cb1   = (const float*)d_in[7];
    const float* cw2   = (const float*)d_in[8];
    const float* cb2   = (const float*)d_in[9];
    const float* xw1   = (const float*)d_in[10];
    const float* xb1   = (const float*)d_in[11];
    const float* xw2   = (const float*)d_in[12];
    const float* xb2   = (const float*)d_in[13];
    const float* nw1   = (const float*)d_in[14];
    const float* nb1   = (const float*)d_in[15];
    const float* nw2   = (const float*)d_in[16];
    const float* nb2   = (const float*)d_in[17];
    float* out = (float*)d_out;

    cudaFuncSetAttribute(k_main, cudaFuncAttributeMaxDynamicSharedMemorySize, SMEM_BYTES);

    k_precomp<<<NBI / 32, 256>>>(feats, ew1, nw1);
    k_tm<<<NBI + NB, 256>>>(coors);
    k_main<<<148, 512, SMEM_BYTES>>>(coors, ew1, eb1, ew2, eb2,
                                     cw1, cb1, cw2, cb2, xw1, xb1, xw2, xb2, out);
    k_node<<<NBI / 16, 256>>>(feats, nw1, nb1, nw2, nb2, out);
}